// round 16
// baseline (speedup 1.0000x reference)
#include <cuda_runtime.h>
#include <cuda_bf16.h>
#include <cuda_fp16.h>
#include <cstdint>
#include <cstring>

// ---------------------------------------------------------------------------
// GraphSAGE (2-layer, mean agg) + graph-mean readout + linear classifier.
// R16: revert to R14 (fp8 gathers, 202.4us — bf16 gather regressed: lost L2
// residency + latency hiding).  Added: dual accumulator banks + esrc prefetch
// in the fp8 gather to break the HADD2 dependency chain.
// ---------------------------------------------------------------------------

#define K_NODES  100000
#define K_EDGES  1600000
#define K_GRAPHS 64
#define K_DIM    128
#define K_CLS    8
#define K_NB     98            // ceil(100000/1024)
#define K_QUADS  (K_NODES * K_DIM / 4)

// scratch (static device memory; no allocations)
__device__ int   g_count [K_NODES];            // zero-invariant
__device__ int   g_rowptr[K_NODES + 1];
__device__ int   g_cursor[K_NODES];
__device__ int   g_esrc  [K_EDGES];            // BYTE offsets (src*128)
__device__ unsigned long long g_state[K_NB];   // packed (flag<<32)|value
__device__ float g_gs1   [K_GRAPHS * K_DIM];   // zero-invariant
__device__ float g_gs2   [K_GRAPHS * K_DIM];   // zero-invariant
__device__ int   g_gcnt  [K_GRAPHS];           // zero-invariant
__device__ __nv_bfloat16 g_hb  [(size_t)K_NODES * K_DIM];   // bf16 h
__device__ __nv_bfloat16 g_mb  [(size_t)K_NODES * K_DIM];   // bf16 mean
__device__ __nv_bfloat16 g_h1b [(size_t)K_NODES * K_DIM];   // bf16 h1
__device__ uint8_t       g_h8  [(size_t)K_NODES * K_DIM];   // fp8 h
__device__ uint8_t       g_h18 [(size_t)K_NODES * K_DIM];   // fp8 h1
__device__ __nv_bfloat16 g_wb  [128 * 256];    // bf16 W [n][k], k<128=W1s,>=128=W1n

// ---------------------------------------------------------------------------
// 0) prep: bf16 + fp8 shadows of h + W bf16 transpose + histogram + state reset
__global__ void k_prep(const float* __restrict__ X, __nv_bfloat16* __restrict__ Y,
                       uint8_t* __restrict__ Y8, const int* __restrict__ dst,
                       const float* __restrict__ W1s, const float* __restrict__ W1n) {
    int i = blockIdx.x * blockDim.x + threadIdx.x;
    if (i < K_NB) g_state[i] = 0ull;
    if (i < 128 * 256) {                       // W transpose + bf16 cvt (once)
        int n = i >> 8, k = i & 255;
        float v = (k < 128) ? W1s[k * 128 + n] : W1n[(k - 128) * 128 + n];
        g_wb[i] = __float2bfloat16(v);
    }
    if (i < K_QUADS) {
        float4 v = *((const float4*)X + i);
        __nv_bfloat162 a = __floats2bfloat162_rn(v.x, v.y);
        __nv_bfloat162 b = __floats2bfloat162_rn(v.z, v.w);
        uint2 u;
        memcpy(&u.x, &a, 4);
        memcpy(&u.y, &b, 4);
        *((uint2*)Y + i) = u;
        unsigned short p01, p23;
        asm("cvt.rn.satfinite.e4m3x2.f32 %0, %1, %2;" : "=h"(p01) : "f"(v.y), "f"(v.x));
        asm("cvt.rn.satfinite.e4m3x2.f32 %0, %1, %2;" : "=h"(p23) : "f"(v.w), "f"(v.z));
        ((uint32_t*)Y8)[i] = (uint32_t)p01 | ((uint32_t)p23 << 16);
    }
    if (i < K_EDGES) atomicAdd(&g_count[dst[i]], 1);
}

// 1) single-pass scan (decoupled lookback, packed flag|value) -> rowptr,cursor
__global__ void k_scan() {
    __shared__ int sm[256];
    __shared__ int sExcl;
    int b = blockIdx.x, t = threadIdx.x;
    int base = b * 1024 + t * 4;
    int c[4];
    int s = 0;
#pragma unroll
    for (int j = 0; j < 4; ++j) {
        int i = base + j;
        c[j] = (i < K_NODES) ? g_count[i] : 0;
        if (i < K_NODES) g_count[i] = 0;       // maintain zero-invariant
        s += c[j];
    }
    sm[t] = s;
    __syncthreads();
    for (int o = 1; o < 256; o <<= 1) {
        int u = (t >= o) ? sm[t - o] : 0;
        __syncthreads();
        sm[t] += u;
        __syncthreads();
    }
    int S = sm[255];
    if (t == 0) {
        if (b == 0) {
            atomicExch(&g_state[0], (2ull << 32) | (unsigned int)S);
            sExcl = 0;
        } else {
            atomicExch(&g_state[b], (1ull << 32) | (unsigned int)S);
            int excl = 0, p = b - 1;
            while (true) {
                unsigned long long v = atomicAdd(&g_state[p], 0ull);
                unsigned int f = (unsigned int)(v >> 32);
                if (f == 0) continue;
                excl += (int)(unsigned int)v;
                if (f == 2) break;
                --p;
            }
            atomicExch(&g_state[b], (2ull << 32) | (unsigned int)(excl + S));
            sExcl = excl;
        }
    }
    __syncthreads();
    int off = sExcl + sm[t] - s;
#pragma unroll
    for (int j = 0; j < 4; ++j) {
        int i = base + j;
        if (i < K_NODES) {
            g_rowptr[i] = off;
            g_cursor[i] = off;
        }
        off += c[j];
    }
    if (b == K_NB - 1 && t == 255) g_rowptr[K_NODES] = sExcl + S;
}

// 2) bucket fill: sort edges by dst; store BYTE offsets (src*128)
__global__ void k_fill(const int* __restrict__ src, const int* __restrict__ dst) {
    int i = blockIdx.x * blockDim.x + threadIdx.x;
    if (i < K_EDGES) {
        int p = atomicAdd(&g_cursor[dst[i]], 1);
        g_esrc[p] = src[i] << 7;               // 128 B per fp8 row
    }
}

// ---------------------------------------------------------------------------
// fp8 quarter-warp gather (esrc holds byte offsets); dual accumulator banks.
__device__ __forceinline__ void dec16(uint4 u, __half2* acc) {
    uint32_t w[4] = {u.x, u.y, u.z, u.w};
#pragma unroll
    for (int i = 0; i < 4; ++i) {
        uint32_t r0, r1;
        asm("cvt.rn.f16x2.e4m3x2 %0, %1;" : "=r"(r0) : "h"((unsigned short)(w[i] & 0xFFFFu)));
        asm("cvt.rn.f16x2.e4m3x2 %0, %1;" : "=r"(r1) : "h"((unsigned short)(w[i] >> 16)));
        __half2 h0, h1;
        memcpy(&h0, &r0, 4);
        memcpy(&h1, &r1, 4);
        acc[2 * i]     = __hadd2(acc[2 * i], h0);
        acc[2 * i + 1] = __hadd2(acc[2 * i + 1], h1);
    }
}
__device__ __forceinline__ __half2 h2shfl_xor(__half2 v, int m) {
    uint32_t u;
    memcpy(&u, &v, 4);
    u = __shfl_xor_sync(0xffffffffu, u, m);
    __half2 r;
    memcpy(&r, &u, 4);
    return r;
}

__device__ __forceinline__ float4 gather_node4(const uint8_t* __restrict__ X8,
                                               int e0, int e1, int quarter, int sub8) {
    const char* base = (const char*)X8 + sub8 * 16;
    __half2 accA[8], accB[8];
    __half2 hz = __float2half2_rn(0.0f);
#pragma unroll
    for (int j = 0; j < 8; ++j) { accA[j] = hz; accB[j] = hz; }

    int e = e0;
    if (e + 8 <= e1) {
        int s0 = g_esrc[e + quarter];
        int s1 = g_esrc[e + 4 + quarter];
        for (; e + 16 <= e1; e += 8) {
            uint4 u0 = *(const uint4*)(base + (uint32_t)s0);
            uint4 u1 = *(const uint4*)(base + (uint32_t)s1);
            s0 = g_esrc[e + 8 + quarter];          // prefetch next indices
            s1 = g_esrc[e + 12 + quarter];
            dec16(u0, accA);
            dec16(u1, accB);
        }
        uint4 u0 = *(const uint4*)(base + (uint32_t)s0);
        uint4 u1 = *(const uint4*)(base + (uint32_t)s1);
        dec16(u0, accA);
        dec16(u1, accB);
        e += 8;
    }
    for (; e < e1; e += 4) {                      // predicated tail
        int idx = e + quarter;
        if (idx < e1) {
            int s = g_esrc[idx];
            uint4 u = *(const uint4*)(base + (uint32_t)s);
            dec16(u, accA);
        }
    }
#pragma unroll
    for (int j = 0; j < 8; ++j) {
        __half2 a = __hadd2(accA[j], accB[j]);
        a = __hadd2(a, h2shfl_xor(a, 8));
        a = __hadd2(a, h2shfl_xor(a, 16));
        accA[j] = a;
    }
    float2 f0 = __half22float2(accA[2 * quarter]);
    float2 f1 = __half22float2(accA[2 * quarter + 1]);
    float4 r;
    r.x = f0.x; r.y = f0.y; r.z = f1.x; r.w = f1.y;
    return r;
}

// 3) SpMM mean (layer 1): warp per node, fp8 gather -> bf16 mean row
__global__ void k_spmm1(const uint8_t* __restrict__ X8,
                        __nv_bfloat16* __restrict__ Y) {
    int w = (blockIdx.x * blockDim.x + threadIdx.x) >> 5;
    int lane = threadIdx.x & 31;
    if (w >= K_NODES) return;
    int e0 = g_rowptr[w], e1 = g_rowptr[w + 1];
    int quarter = lane >> 3, sub8 = lane & 7;
    float4 a = gather_node4(X8, e0, e1, quarter, sub8);
    float inv = (e1 > e0) ? 1.0f / (float)(e1 - e0) : 0.0f;
    __nv_bfloat162 p0 = __floats2bfloat162_rn(a.x * inv, a.y * inv);
    __nv_bfloat162 p1 = __floats2bfloat162_rn(a.z * inv, a.w * inv);
    uint2 st;
    memcpy(&st.x, &p0, 4);
    memcpy(&st.y, &p1, 4);
    *((uint2*)(Y + (size_t)w * K_DIM + sub8 * 16 + quarter * 4)) = st;
}

// ---------------------------------------------------------------------------
// 4) bf16 m16n8k16 dual GEMM: h1 = relu(A1@W1 + A2@W2 + bias)
//    W read raw from pre-converted bf16 [n][256k] buffer.
__device__ __forceinline__ void mma_bf16(float* c, uint32_t a0, uint32_t a1,
                                         uint32_t a2, uint32_t a3,
                                         uint32_t b0, uint32_t b1) {
    asm volatile(
        "mma.sync.aligned.m16n8k16.row.col.f32.bf16.bf16.f32 "
        "{%0,%1,%2,%3}, {%4,%5,%6,%7}, {%8,%9}, {%0,%1,%2,%3};"
        : "+f"(c[0]), "+f"(c[1]), "+f"(c[2]), "+f"(c[3])
        : "r"(a0), "r"(a1), "r"(a2), "r"(a3), "r"(b0), "r"(b1));
}

#define XPITCH 20   // words per 32-k row (16 data + 4 pad); mult of 4

__global__ __launch_bounds__(256, 2)
void k_gemm_bf16(const __nv_bfloat16* __restrict__ A1,
                 const __nv_bfloat16* __restrict__ A2,
                 const __nv_bfloat16* __restrict__ WB,   // [128n][256k] bf16
                 const float* __restrict__ bias,
                 __nv_bfloat16* __restrict__ Cb, uint8_t* __restrict__ C8, int M) {
    __shared__ __align__(16) uint32_t Xs[128 * XPITCH];
    __shared__ __align__(16) uint32_t Ws[128 * XPITCH];
    int tid = threadIdx.x, wid = tid >> 5, lane = tid & 31;
    int grp = lane >> 2, tig = lane & 3;
    int warpM = wid & 3, warpN = wid >> 2;
    int rowBase = blockIdx.x * 128;
    int wr = warpM * 32;
    int wn = warpN * 64;

    int ar = tid >> 1, aq = tid & 1;               // A staging
    int n0 = tid >> 1, j0 = (tid & 1) << 1;        // W staging: 2 uint4/thread

    float acc[2][8][4];
#pragma unroll
    for (int mt = 0; mt < 2; ++mt)
#pragma unroll
        for (int nt = 0; nt < 8; ++nt)
#pragma unroll
            for (int q = 0; q < 4; ++q) acc[mt][nt][q] = 0.0f;

    uint4 va[2], wv[2];
    {
        int grow = rowBase + ar; if (grow >= M) grow = M - 1;
        const uint4* ap = (const uint4*)(A1 + (size_t)grow * K_DIM + aq * 16);
        va[0] = ap[0];
        va[1] = ap[1];
        const uint4* wp = (const uint4*)(WB + n0 * 256 + j0 * 8);
        wv[0] = wp[0];
        wv[1] = wp[1];
    }

#pragma unroll 1
    for (int cc = 0; cc < 8; ++cc) {
        __syncthreads();
        {
            int base = ar * XPITCH + aq * 8;
            *(uint4*)&Xs[base] = va[0];
            *(uint4*)&Xs[base + 4] = va[1];
        }
        {
            int base = n0 * XPITCH + j0 * 4;
            *(uint4*)&Ws[base] = wv[0];
            *(uint4*)&Ws[base + 4] = wv[1];
        }
        __syncthreads();
        if (cc < 7) {
            int nc = cc + 1;
            const __nv_bfloat16* A = (nc >= 4) ? A2 : A1;
            int k0 = (nc & 3) * 32;
            int grow = rowBase + ar; if (grow >= M) grow = M - 1;
            const uint4* ap = (const uint4*)(A + (size_t)grow * K_DIM + k0 + aq * 16);
            va[0] = ap[0];
            va[1] = ap[1];
            const uint4* wp = (const uint4*)(WB + n0 * 256 + nc * 32 + j0 * 8);
            wv[0] = wp[0];
            wv[1] = wp[1];
        }
#pragma unroll
        for (int ks = 0; ks < 2; ++ks) {
            int kw = ks * 8;
            uint32_t af[2][4];
#pragma unroll
            for (int mt = 0; mt < 2; ++mt) {
                int r = wr + mt * 16 + grp;
                af[mt][0] = Xs[r * XPITCH + kw + tig];
                af[mt][1] = Xs[(r + 8) * XPITCH + kw + tig];
                af[mt][2] = Xs[r * XPITCH + kw + tig + 4];
                af[mt][3] = Xs[(r + 8) * XPITCH + kw + tig + 4];
            }
#pragma unroll
            for (int nt = 0; nt < 8; ++nt) {
                int n = wn + nt * 8 + grp;
                uint32_t b0 = Ws[n * XPITCH + kw + tig];
                uint32_t b1 = Ws[n * XPITCH + kw + tig + 4];
                mma_bf16(acc[0][nt], af[0][0], af[0][1], af[0][2], af[0][3], b0, b1);
                mma_bf16(acc[1][nt], af[1][0], af[1][1], af[1][2], af[1][3], b0, b1);
            }
        }
    }

    // epilogue: bias + ReLU; bf16 + fp8 shadow stores
#pragma unroll
    for (int mt = 0; mt < 2; ++mt) {
        int r0g = rowBase + wr + mt * 16 + grp;
        int r1g = r0g + 8;
#pragma unroll
        for (int nt = 0; nt < 8; ++nt) {
            int col = wn + nt * 8 + 2 * tig;
            float2 bv = *(const float2*)&bias[col];
            if (r0g < M) {
                float vx = fmaxf(acc[mt][nt][0] + bv.x, 0.0f);
                float vy = fmaxf(acc[mt][nt][1] + bv.y, 0.0f);
                __nv_bfloat162 hb = __floats2bfloat162_rn(vx, vy);
                *(__nv_bfloat162*)&Cb[(size_t)r0g * K_DIM + col] = hb;
                unsigned short p;
                asm("cvt.rn.satfinite.e4m3x2.f32 %0, %1, %2;" : "=h"(p) : "f"(vy), "f"(vx));
                *(unsigned short*)(C8 + (size_t)r0g * K_DIM + col) = p;
            }
            if (r1g < M) {
                float vx = fmaxf(acc[mt][nt][2] + bv.x, 0.0f);
                float vy = fmaxf(acc[mt][nt][3] + bv.y, 0.0f);
                __nv_bfloat162 hb = __floats2bfloat162_rn(vx, vy);
                *(__nv_bfloat162*)&Cb[(size_t)r1g * K_DIM + col] = hb;
                unsigned short p;
                asm("cvt.rn.satfinite.e4m3x2.f32 %0, %1, %2;" : "=h"(p) : "f"(vy), "f"(vx));
                *(unsigned short*)(C8 + (size_t)r1g * K_DIM + col) = p;
            }
        }
    }
}

// ---------------------------------------------------------------------------
// 5) fused SpMM2 + per-graph sums: block = 16 warps = 16 graph-sorted nodes.
__global__ __launch_bounds__(512)
void k_spmm_gs2(const uint8_t* __restrict__ X8,          // fp8 h1
                const __nv_bfloat16* __restrict__ H,      // bf16 h1
                const int* __restrict__ gid) {
    __shared__ float smean[16][K_DIM];
    __shared__ float sh1[16][K_DIM];
    __shared__ int sg[16];
    int wid = threadIdx.x >> 5, lane = threadIdx.x & 31;
    int node = blockIdx.x * 16 + wid;                     // 100000 = 6250*16
    int e0 = g_rowptr[node], e1 = g_rowptr[node + 1];
    int quarter = lane >> 3, sub8 = lane & 7;
    float4 a = gather_node4(X8, e0, e1, quarter, sub8);
    float inv = (e1 > e0) ? 1.0f / (float)(e1 - e0) : 0.0f;
    float4 mv;
    mv.x = a.x * inv; mv.y = a.y * inv; mv.z = a.z * inv; mv.w = a.w * inv;
    *(float4*)&smean[wid][sub8 * 16 + quarter * 4] = mv;
    uint2 u = *((const uint2*)(H + (size_t)node * K_DIM) + lane);
    float4 hv;
    hv.x = __uint_as_float(u.x << 16);
    hv.y = __uint_as_float(u.x & 0xFFFF0000u);
    hv.z = __uint_as_float(u.y << 16);
    hv.w = __uint_as_float(u.y & 0xFFFF0000u);
    *(float4*)&sh1[wid][lane * 4] = hv;
    if (lane == 0) sg[wid] = gid[node];
    __syncthreads();

    int t = threadIdx.x;
    if (t < 256) {
        int d = t & 127;
        float* dstArr = (t < 128) ? g_gs1 : g_gs2;
        int cur = sg[0];
        float acc = 0.0f;
#pragma unroll
        for (int w = 0; w < 16; ++w) {
            int g = sg[w];
            float v = (t < 128) ? sh1[w][d] : smean[w][d];
            if (g != cur) {
                atomicAdd(&dstArr[cur * K_DIM + d], acc);
                acc = 0.0f; cur = g;
            }
            acc += v;
        }
        atomicAdd(&dstArr[cur * K_DIM + d], acc);
    } else if (t == 256) {
        int cur = sg[0], c = 0;
#pragma unroll
        for (int w = 0; w < 16; ++w) {
            int g = sg[w];
            if (g != cur) { atomicAdd(&g_gcnt[cur], c); c = 0; cur = g; }
            ++c;
        }
        atomicAdd(&g_gcnt[cur], c);
    }
}

// ---------------------------------------------------------------------------
// 6) fused: hg = (gs1@W2s + gs2@W2n)/cnt + b2 ; out = [hg|perm]@Wc + bc
//    Re-zeroes gs1/gs2/gcnt for the next kernel_launch call.
__global__ void k_hgcls(const float* __restrict__ W2s, const float* __restrict__ W2n,
                        const float* __restrict__ b2,
                        const float* __restrict__ perm,
                        const float* __restrict__ Wc,
                        const float* __restrict__ bc,
                        float* __restrict__ out) {
    __shared__ float s1[K_DIM], s2[K_DIM], hgs[K_DIM];
    __shared__ float red[K_CLS];
    __shared__ int scnt;
    int g = blockIdx.x, d = threadIdx.x;
    s1[d] = g_gs1[g * K_DIM + d];
    s2[d] = g_gs2[g * K_DIM + d];
    if (d == 0) scnt = g_gcnt[g];
    if (d < K_CLS) red[d] = bc[d];
    __syncthreads();
    g_gs1[g * K_DIM + d] = 0.0f;       // zero-invariant for next call
    g_gs2[g * K_DIM + d] = 0.0f;
    if (d == 0) g_gcnt[g] = 0;
    float acc = 0.0f;
#pragma unroll 4
    for (int k = 0; k < K_DIM; ++k)
        acc += s1[k] * W2s[k * K_DIM + d] + s2[k] * W2n[k * K_DIM + d];
    int cnt = scnt;
    float inv = 1.0f / (float)(cnt > 1 ? cnt : 1);
    hgs[d] = acc * inv + b2[d];
    __syncthreads();
    if (d < 64) {
        int c = d & 7, seg = d >> 3;
        int k0 = seg * 32;
        float p = 0.0f;
#pragma unroll 4
        for (int k = k0; k < k0 + 32; ++k) {
            float val = (k < K_DIM) ? hgs[k] : perm[g * K_DIM + (k - K_DIM)];
            p += val * Wc[k * K_CLS + c];
        }
        atomicAdd(&red[c], p);
    }
    __syncthreads();
    if (d < K_CLS) out[g * K_CLS + d] = red[d];
}

// ---------------------------------------------------------------------------
extern "C" void kernel_launch(void* const* d_in, const int* in_sizes, int n_in,
                              void* d_out, int out_size) {
    const float* h    = (const float*)d_in[0];
    const float* perm = (const float*)d_in[1];
    const int*   src  = (const int*)  d_in[2];
    const int*   dst  = (const int*)  d_in[3];
    const int*   gid  = (const int*)  d_in[4];
    const float* W1s  = (const float*)d_in[5];
    const float* W1n  = (const float*)d_in[6];
    const float* b1   = (const float*)d_in[7];
    const float* W2s  = (const float*)d_in[8];
    const float* W2n  = (const float*)d_in[9];
    const float* b2   = (const float*)d_in[10];
    const float* Wc   = (const float*)d_in[11];
    const float* bc   = (const float*)d_in[12];
    float* out = (float*)d_out;
    (void)in_sizes; (void)n_in; (void)out_size;

    __nv_bfloat16* hbb;     cudaGetSymbolAddress((void**)&hbb,   g_hb);
    __nv_bfloat16* mbb;     cudaGetSymbolAddress((void**)&mbb,   g_mb);
    __nv_bfloat16* h1bb;    cudaGetSymbolAddress((void**)&h1bb,  g_h1b);
    uint8_t* h8;            cudaGetSymbolAddress((void**)&h8,    g_h8);
    uint8_t* h18;           cudaGetSymbolAddress((void**)&h18,   g_h18);
    __nv_bfloat16* wbb;     cudaGetSymbolAddress((void**)&wbb,   g_wb);

    // CSR build (3 launches)
    k_prep<<<(K_QUADS + 255) / 256, 256>>>(h, hbb, h8, dst, W1s, W1n);
    k_scan<<<K_NB, 256>>>();
    k_fill<<<(K_EDGES + 255) / 256, 256>>>(src, dst);

    int spmmBlocks = (K_NODES * 32 + 255) / 256;
    int gemmBlocks = (K_NODES + 127) / 128;

    // layer 1
    k_spmm1<<<spmmBlocks, 256>>>(h8, mbb);
    k_gemm_bf16<<<gemmBlocks, 256>>>(hbb, mbb, wbb, b1, h1bb, h18, K_NODES);

    // layer 2 on graph means: fused SpMM2 + per-graph sums, then readout
    k_spmm_gs2<<<K_NODES / 16, 512>>>(h18, h1bb, gid);
    k_hgcls<<<K_GRAPHS, K_DIM>>>(W2s, W2n, b2, perm, Wc, bc, out);
}

// round 17
// speedup vs baseline: 1.0791x; 1.0791x over previous
#include <cuda_runtime.h>
#include <cuda_bf16.h>
#include <cuda_fp16.h>
#include <cstdint>
#include <cstring>

// ---------------------------------------------------------------------------
// GraphSAGE (2-layer, mean agg) + graph-mean readout + linear classifier.
// R17: exact revert to R14 (202.4us best).  R15 (bf16 gather) and R16 (dual
// accumulator banks) both regressed by trading occupancy for per-warp ILP;
// the R14 fp8 gather at 32 regs / 82% occupancy is the local optimum.
// ---------------------------------------------------------------------------

#define K_NODES  100000
#define K_EDGES  1600000
#define K_GRAPHS 64
#define K_DIM    128
#define K_CLS    8
#define K_NB     98            // ceil(100000/1024)
#define K_QUADS  (K_NODES * K_DIM / 4)

// scratch (static device memory; no allocations)
__device__ int   g_count [K_NODES];            // zero-invariant
__device__ int   g_rowptr[K_NODES + 1];
__device__ int   g_cursor[K_NODES];
__device__ int   g_esrc  [K_EDGES];            // BYTE offsets (src*128)
__device__ unsigned long long g_state[K_NB];   // packed (flag<<32)|value
__device__ float g_gs1   [K_GRAPHS * K_DIM];   // zero-invariant
__device__ float g_gs2   [K_GRAPHS * K_DIM];   // zero-invariant
__device__ int   g_gcnt  [K_GRAPHS];           // zero-invariant
__device__ __nv_bfloat16 g_hb  [(size_t)K_NODES * K_DIM];   // bf16 h
__device__ __nv_bfloat16 g_mb  [(size_t)K_NODES * K_DIM];   // bf16 mean
__device__ __nv_bfloat16 g_h1b [(size_t)K_NODES * K_DIM];   // bf16 h1
__device__ uint8_t       g_h8  [(size_t)K_NODES * K_DIM];   // fp8 h
__device__ uint8_t       g_h18 [(size_t)K_NODES * K_DIM];   // fp8 h1
__device__ __nv_bfloat16 g_wb  [128 * 256];    // bf16 W [n][k], k<128=W1s,>=128=W1n

// ---------------------------------------------------------------------------
// 0) prep: bf16 + fp8 shadows of h + W bf16 transpose + histogram + state reset
__global__ void k_prep(const float* __restrict__ X, __nv_bfloat16* __restrict__ Y,
                       uint8_t* __restrict__ Y8, const int* __restrict__ dst,
                       const float* __restrict__ W1s, const float* __restrict__ W1n) {
    int i = blockIdx.x * blockDim.x + threadIdx.x;
    if (i < K_NB) g_state[i] = 0ull;
    if (i < 128 * 256) {                       // W transpose + bf16 cvt (once)
        int n = i >> 8, k = i & 255;
        float v = (k < 128) ? W1s[k * 128 + n] : W1n[(k - 128) * 128 + n];
        g_wb[i] = __float2bfloat16(v);
    }
    if (i < K_QUADS) {
        float4 v = *((const float4*)X + i);
        __nv_bfloat162 a = __floats2bfloat162_rn(v.x, v.y);
        __nv_bfloat162 b = __floats2bfloat162_rn(v.z, v.w);
        uint2 u;
        memcpy(&u.x, &a, 4);
        memcpy(&u.y, &b, 4);
        *((uint2*)Y + i) = u;
        unsigned short p01, p23;
        asm("cvt.rn.satfinite.e4m3x2.f32 %0, %1, %2;" : "=h"(p01) : "f"(v.y), "f"(v.x));
        asm("cvt.rn.satfinite.e4m3x2.f32 %0, %1, %2;" : "=h"(p23) : "f"(v.w), "f"(v.z));
        ((uint32_t*)Y8)[i] = (uint32_t)p01 | ((uint32_t)p23 << 16);
    }
    if (i < K_EDGES) atomicAdd(&g_count[dst[i]], 1);
}

// 1) single-pass scan (decoupled lookback, packed flag|value) -> rowptr,cursor
__global__ void k_scan() {
    __shared__ int sm[256];
    __shared__ int sExcl;
    int b = blockIdx.x, t = threadIdx.x;
    int base = b * 1024 + t * 4;
    int c[4];
    int s = 0;
#pragma unroll
    for (int j = 0; j < 4; ++j) {
        int i = base + j;
        c[j] = (i < K_NODES) ? g_count[i] : 0;
        if (i < K_NODES) g_count[i] = 0;       // maintain zero-invariant
        s += c[j];
    }
    sm[t] = s;
    __syncthreads();
    for (int o = 1; o < 256; o <<= 1) {
        int u = (t >= o) ? sm[t - o] : 0;
        __syncthreads();
        sm[t] += u;
        __syncthreads();
    }
    int S = sm[255];
    if (t == 0) {
        if (b == 0) {
            atomicExch(&g_state[0], (2ull << 32) | (unsigned int)S);
            sExcl = 0;
        } else {
            atomicExch(&g_state[b], (1ull << 32) | (unsigned int)S);
            int excl = 0, p = b - 1;
            while (true) {
                unsigned long long v = atomicAdd(&g_state[p], 0ull);
                unsigned int f = (unsigned int)(v >> 32);
                if (f == 0) continue;
                excl += (int)(unsigned int)v;
                if (f == 2) break;
                --p;
            }
            atomicExch(&g_state[b], (2ull << 32) | (unsigned int)(excl + S));
            sExcl = excl;
        }
    }
    __syncthreads();
    int off = sExcl + sm[t] - s;
#pragma unroll
    for (int j = 0; j < 4; ++j) {
        int i = base + j;
        if (i < K_NODES) {
            g_rowptr[i] = off;
            g_cursor[i] = off;
        }
        off += c[j];
    }
    if (b == K_NB - 1 && t == 255) g_rowptr[K_NODES] = sExcl + S;
}

// 2) bucket fill: sort edges by dst; store BYTE offsets (src*128)
__global__ void k_fill(const int* __restrict__ src, const int* __restrict__ dst) {
    int i = blockIdx.x * blockDim.x + threadIdx.x;
    if (i < K_EDGES) {
        int p = atomicAdd(&g_cursor[dst[i]], 1);
        g_esrc[p] = src[i] << 7;               // 128 B per fp8 row
    }
}

// ---------------------------------------------------------------------------
// fp8 quarter-warp gather (esrc holds byte offsets)
__device__ __forceinline__ void dec16(uint4 u, __half2* acc) {
    uint32_t w[4] = {u.x, u.y, u.z, u.w};
#pragma unroll
    for (int i = 0; i < 4; ++i) {
        uint32_t r0, r1;
        asm("cvt.rn.f16x2.e4m3x2 %0, %1;" : "=r"(r0) : "h"((unsigned short)(w[i] & 0xFFFFu)));
        asm("cvt.rn.f16x2.e4m3x2 %0, %1;" : "=r"(r1) : "h"((unsigned short)(w[i] >> 16)));
        __half2 h0, h1;
        memcpy(&h0, &r0, 4);
        memcpy(&h1, &r1, 4);
        acc[2 * i]     = __hadd2(acc[2 * i], h0);
        acc[2 * i + 1] = __hadd2(acc[2 * i + 1], h1);
    }
}
__device__ __forceinline__ __half2 h2shfl_xor(__half2 v, int m) {
    uint32_t u;
    memcpy(&u, &v, 4);
    u = __shfl_xor_sync(0xffffffffu, u, m);
    __half2 r;
    memcpy(&r, &u, 4);
    return r;
}

__device__ __forceinline__ float4 gather_node4(const uint8_t* __restrict__ X8,
                                               int e0, int e1, int quarter, int sub8) {
    const char* base = (const char*)X8 + sub8 * 16;
    __half2 acc[8];
    __half2 hz = __float2half2_rn(0.0f);
#pragma unroll
    for (int j = 0; j < 8; ++j) acc[j] = hz;

    int e = e0;
    for (; e + 8 <= e1; e += 8) {
        int s0 = g_esrc[e + quarter];
        int s1 = g_esrc[e + 4 + quarter];
        uint4 u0 = *(const uint4*)(base + (uint32_t)s0);
        uint4 u1 = *(const uint4*)(base + (uint32_t)s1);
        dec16(u0, acc);
        dec16(u1, acc);
    }
    for (; e < e1; e += 4) {
        int idx = e + quarter;
        if (idx < e1) {
            int s = g_esrc[idx];
            uint4 u = *(const uint4*)(base + (uint32_t)s);
            dec16(u, acc);
        }
    }
#pragma unroll
    for (int j = 0; j < 8; ++j) {
        acc[j] = __hadd2(acc[j], h2shfl_xor(acc[j], 8));
        acc[j] = __hadd2(acc[j], h2shfl_xor(acc[j], 16));
    }
    float2 f0 = __half22float2(acc[2 * quarter]);
    float2 f1 = __half22float2(acc[2 * quarter + 1]);
    float4 r;
    r.x = f0.x; r.y = f0.y; r.z = f1.x; r.w = f1.y;
    return r;
}

// 3) SpMM mean (layer 1): warp per node, fp8 gather -> bf16 mean row
__global__ void k_spmm1(const uint8_t* __restrict__ X8,
                        __nv_bfloat16* __restrict__ Y) {
    int w = (blockIdx.x * blockDim.x + threadIdx.x) >> 5;
    int lane = threadIdx.x & 31;
    if (w >= K_NODES) return;
    int e0 = g_rowptr[w], e1 = g_rowptr[w + 1];
    int quarter = lane >> 3, sub8 = lane & 7;
    float4 a = gather_node4(X8, e0, e1, quarter, sub8);
    float inv = (e1 > e0) ? 1.0f / (float)(e1 - e0) : 0.0f;
    __nv_bfloat162 p0 = __floats2bfloat162_rn(a.x * inv, a.y * inv);
    __nv_bfloat162 p1 = __floats2bfloat162_rn(a.z * inv, a.w * inv);
    uint2 st;
    memcpy(&st.x, &p0, 4);
    memcpy(&st.y, &p1, 4);
    *((uint2*)(Y + (size_t)w * K_DIM + sub8 * 16 + quarter * 4)) = st;
}

// ---------------------------------------------------------------------------
// 4) bf16 m16n8k16 dual GEMM: h1 = relu(A1@W1 + A2@W2 + bias)
//    W read raw from pre-converted bf16 [n][256k] buffer.
__device__ __forceinline__ void mma_bf16(float* c, uint32_t a0, uint32_t a1,
                                         uint32_t a2, uint32_t a3,
                                         uint32_t b0, uint32_t b1) {
    asm volatile(
        "mma.sync.aligned.m16n8k16.row.col.f32.bf16.bf16.f32 "
        "{%0,%1,%2,%3}, {%4,%5,%6,%7}, {%8,%9}, {%0,%1,%2,%3};"
        : "+f"(c[0]), "+f"(c[1]), "+f"(c[2]), "+f"(c[3])
        : "r"(a0), "r"(a1), "r"(a2), "r"(a3), "r"(b0), "r"(b1));
}

#define XPITCH 20   // words per 32-k row (16 data + 4 pad); mult of 4

__global__ __launch_bounds__(256, 2)
void k_gemm_bf16(const __nv_bfloat16* __restrict__ A1,
                 const __nv_bfloat16* __restrict__ A2,
                 const __nv_bfloat16* __restrict__ WB,   // [128n][256k] bf16
                 const float* __restrict__ bias,
                 __nv_bfloat16* __restrict__ Cb, uint8_t* __restrict__ C8, int M) {
    __shared__ __align__(16) uint32_t Xs[128 * XPITCH];
    __shared__ __align__(16) uint32_t Ws[128 * XPITCH];
    int tid = threadIdx.x, wid = tid >> 5, lane = tid & 31;
    int grp = lane >> 2, tig = lane & 3;
    int warpM = wid & 3, warpN = wid >> 2;
    int rowBase = blockIdx.x * 128;
    int wr = warpM * 32;
    int wn = warpN * 64;

    int ar = tid >> 1, aq = tid & 1;               // A staging
    int n0 = tid >> 1, j0 = (tid & 1) << 1;        // W staging: 2 uint4/thread

    float acc[2][8][4];
#pragma unroll
    for (int mt = 0; mt < 2; ++mt)
#pragma unroll
        for (int nt = 0; nt < 8; ++nt)
#pragma unroll
            for (int q = 0; q < 4; ++q) acc[mt][nt][q] = 0.0f;

    uint4 va[2], wv[2];
    {
        int grow = rowBase + ar; if (grow >= M) grow = M - 1;
        const uint4* ap = (const uint4*)(A1 + (size_t)grow * K_DIM + aq * 16);
        va[0] = ap[0];
        va[1] = ap[1];
        const uint4* wp = (const uint4*)(WB + n0 * 256 + j0 * 8);
        wv[0] = wp[0];
        wv[1] = wp[1];
    }

#pragma unroll 1
    for (int cc = 0; cc < 8; ++cc) {
        __syncthreads();
        {
            int base = ar * XPITCH + aq * 8;
            *(uint4*)&Xs[base] = va[0];
            *(uint4*)&Xs[base + 4] = va[1];
        }
        {
            int base = n0 * XPITCH + j0 * 4;
            *(uint4*)&Ws[base] = wv[0];
            *(uint4*)&Ws[base + 4] = wv[1];
        }
        __syncthreads();
        if (cc < 7) {
            int nc = cc + 1;
            const __nv_bfloat16* A = (nc >= 4) ? A2 : A1;
            int k0 = (nc & 3) * 32;
            int grow = rowBase + ar; if (grow >= M) grow = M - 1;
            const uint4* ap = (const uint4*)(A + (size_t)grow * K_DIM + k0 + aq * 16);
            va[0] = ap[0];
            va[1] = ap[1];
            const uint4* wp = (const uint4*)(WB + n0 * 256 + nc * 32 + j0 * 8);
            wv[0] = wp[0];
            wv[1] = wp[1];
        }
#pragma unroll
        for (int ks = 0; ks < 2; ++ks) {
            int kw = ks * 8;
            uint32_t af[2][4];
#pragma unroll
            for (int mt = 0; mt < 2; ++mt) {
                int r = wr + mt * 16 + grp;
                af[mt][0] = Xs[r * XPITCH + kw + tig];
                af[mt][1] = Xs[(r + 8) * XPITCH + kw + tig];
                af[mt][2] = Xs[r * XPITCH + kw + tig + 4];
                af[mt][3] = Xs[(r + 8) * XPITCH + kw + tig + 4];
            }
#pragma unroll
            for (int nt = 0; nt < 8; ++nt) {
                int n = wn + nt * 8 + grp;
                uint32_t b0 = Ws[n * XPITCH + kw + tig];
                uint32_t b1 = Ws[n * XPITCH + kw + tig + 4];
                mma_bf16(acc[0][nt], af[0][0], af[0][1], af[0][2], af[0][3], b0, b1);
                mma_bf16(acc[1][nt], af[1][0], af[1][1], af[1][2], af[1][3], b0, b1);
            }
        }
    }

    // epilogue: bias + ReLU; bf16 + fp8 shadow stores
#pragma unroll
    for (int mt = 0; mt < 2; ++mt) {
        int r0g = rowBase + wr + mt * 16 + grp;
        int r1g = r0g + 8;
#pragma unroll
        for (int nt = 0; nt < 8; ++nt) {
            int col = wn + nt * 8 + 2 * tig;
            float2 bv = *(const float2*)&bias[col];
            if (r0g < M) {
                float vx = fmaxf(acc[mt][nt][0] + bv.x, 0.0f);
                float vy = fmaxf(acc[mt][nt][1] + bv.y, 0.0f);
                __nv_bfloat162 hb = __floats2bfloat162_rn(vx, vy);
                *(__nv_bfloat162*)&Cb[(size_t)r0g * K_DIM + col] = hb;
                unsigned short p;
                asm("cvt.rn.satfinite.e4m3x2.f32 %0, %1, %2;" : "=h"(p) : "f"(vy), "f"(vx));
                *(unsigned short*)(C8 + (size_t)r0g * K_DIM + col) = p;
            }
            if (r1g < M) {
                float vx = fmaxf(acc[mt][nt][2] + bv.x, 0.0f);
                float vy = fmaxf(acc[mt][nt][3] + bv.y, 0.0f);
                __nv_bfloat162 hb = __floats2bfloat162_rn(vx, vy);
                *(__nv_bfloat162*)&Cb[(size_t)r1g * K_DIM + col] = hb;
                unsigned short p;
                asm("cvt.rn.satfinite.e4m3x2.f32 %0, %1, %2;" : "=h"(p) : "f"(vy), "f"(vx));
                *(unsigned short*)(C8 + (size_t)r1g * K_DIM + col) = p;
            }
        }
    }
}

// ---------------------------------------------------------------------------
// 5) fused SpMM2 + per-graph sums: block = 16 warps = 16 graph-sorted nodes.
__global__ __launch_bounds__(512)
void k_spmm_gs2(const uint8_t* __restrict__ X8,          // fp8 h1
                const __nv_bfloat16* __restrict__ H,      // bf16 h1
                const int* __restrict__ gid) {
    __shared__ float smean[16][K_DIM];
    __shared__ float sh1[16][K_DIM];
    __shared__ int sg[16];
    int wid = threadIdx.x >> 5, lane = threadIdx.x & 31;
    int node = blockIdx.x * 16 + wid;                     // 100000 = 6250*16
    int e0 = g_rowptr[node], e1 = g_rowptr[node + 1];
    int quarter = lane >> 3, sub8 = lane & 7;
    float4 a = gather_node4(X8, e0, e1, quarter, sub8);
    float inv = (e1 > e0) ? 1.0f / (float)(e1 - e0) : 0.0f;
    float4 mv;
    mv.x = a.x * inv; mv.y = a.y * inv; mv.z = a.z * inv; mv.w = a.w * inv;
    *(float4*)&smean[wid][sub8 * 16 + quarter * 4] = mv;
    uint2 u = *((const uint2*)(H + (size_t)node * K_DIM) + lane);
    float4 hv;
    hv.x = __uint_as_float(u.x << 16);
    hv.y = __uint_as_float(u.x & 0xFFFF0000u);
    hv.z = __uint_as_float(u.y << 16);
    hv.w = __uint_as_float(u.y & 0xFFFF0000u);
    *(float4*)&sh1[wid][lane * 4] = hv;
    if (lane == 0) sg[wid] = gid[node];
    __syncthreads();

    int t = threadIdx.x;
    if (t < 256) {
        int d = t & 127;
        float* dstArr = (t < 128) ? g_gs1 : g_gs2;
        int cur = sg[0];
        float acc = 0.0f;
#pragma unroll
        for (int w = 0; w < 16; ++w) {
            int g = sg[w];
            float v = (t < 128) ? sh1[w][d] : smean[w][d];
            if (g != cur) {
                atomicAdd(&dstArr[cur * K_DIM + d], acc);
                acc = 0.0f; cur = g;
            }
            acc += v;
        }
        atomicAdd(&dstArr[cur * K_DIM + d], acc);
    } else if (t == 256) {
        int cur = sg[0], c = 0;
#pragma unroll
        for (int w = 0; w < 16; ++w) {
            int g = sg[w];
            if (g != cur) { atomicAdd(&g_gcnt[cur], c); c = 0; cur = g; }
            ++c;
        }
        atomicAdd(&g_gcnt[cur], c);
    }
}

// ---------------------------------------------------------------------------
// 6) fused: hg = (gs1@W2s + gs2@W2n)/cnt + b2 ; out = [hg|perm]@Wc + bc
//    Re-zeroes gs1/gs2/gcnt for the next kernel_launch call.
__global__ void k_hgcls(const float* __restrict__ W2s, const float* __restrict__ W2n,
                        const float* __restrict__ b2,
                        const float* __restrict__ perm,
                        const float* __restrict__ Wc,
                        const float* __restrict__ bc,
                        float* __restrict__ out) {
    __shared__ float s1[K_DIM], s2[K_DIM], hgs[K_DIM];
    __shared__ float red[K_CLS];
    __shared__ int scnt;
    int g = blockIdx.x, d = threadIdx.x;
    s1[d] = g_gs1[g * K_DIM + d];
    s2[d] = g_gs2[g * K_DIM + d];
    if (d == 0) scnt = g_gcnt[g];
    if (d < K_CLS) red[d] = bc[d];
    __syncthreads();
    g_gs1[g * K_DIM + d] = 0.0f;       // zero-invariant for next call
    g_gs2[g * K_DIM + d] = 0.0f;
    if (d == 0) g_gcnt[g] = 0;
    float acc = 0.0f;
#pragma unroll 4
    for (int k = 0; k < K_DIM; ++k)
        acc += s1[k] * W2s[k * K_DIM + d] + s2[k] * W2n[k * K_DIM + d];
    int cnt = scnt;
    float inv = 1.0f / (float)(cnt > 1 ? cnt : 1);
    hgs[d] = acc * inv + b2[d];
    __syncthreads();
    if (d < 64) {
        int c = d & 7, seg = d >> 3;
        int k0 = seg * 32;
        float p = 0.0f;
#pragma unroll 4
        for (int k = k0; k < k0 + 32; ++k) {
            float val = (k < K_DIM) ? hgs[k] : perm[g * K_DIM + (k - K_DIM)];
            p += val * Wc[k * K_CLS + c];
        }
        atomicAdd(&red[c], p);
    }
    __syncthreads();
    if (d < K_CLS) out[g * K_CLS + d] = red[d];
}

// ---------------------------------------------------------------------------
extern "C" void kernel_launch(void* const* d_in, const int* in_sizes, int n_in,
                              void* d_out, int out_size) {
    const float* h    = (const float*)d_in[0];
    const float* perm = (const float*)d_in[1];
    const int*   src  = (const int*)  d_in[2];
    const int*   dst  = (const int*)  d_in[3];
    const int*   gid  = (const int*)  d_in[4];
    const float* W1s  = (const float*)d_in[5];
    const float* W1n  = (const float*)d_in[6];
    const float* b1   = (const float*)d_in[7];
    const float* W2s  = (const float*)d_in[8];
    const float* W2n  = (const float*)d_in[9];
    const float* b2   = (const float*)d_in[10];
    const float* Wc   = (const float*)d_in[11];
    const float* bc   = (const float*)d_in[12];
    float* out = (float*)d_out;
    (void)in_sizes; (void)n_in; (void)out_size;

    __nv_bfloat16* hbb;     cudaGetSymbolAddress((void**)&hbb,   g_hb);
    __nv_bfloat16* mbb;     cudaGetSymbolAddress((void**)&mbb,   g_mb);
    __nv_bfloat16* h1bb;    cudaGetSymbolAddress((void**)&h1bb,  g_h1b);
    uint8_t* h8;            cudaGetSymbolAddress((void**)&h8,    g_h8);
    uint8_t* h18;           cudaGetSymbolAddress((void**)&h18,   g_h18);
    __nv_bfloat16* wbb;     cudaGetSymbolAddress((void**)&wbb,   g_wb);

    // CSR build (3 launches)
    k_prep<<<(K_QUADS + 255) / 256, 256>>>(h, hbb, h8, dst, W1s, W1n);
    k_scan<<<K_NB, 256>>>();
    k_fill<<<(K_EDGES + 255) / 256, 256>>>(src, dst);

    int spmmBlocks = (K_NODES * 32 + 255) / 256;
    int gemmBlocks = (K_NODES + 127) / 128;

    // layer 1
    k_spmm1<<<spmmBlocks, 256>>>(h8, mbb);
    k_gemm_bf16<<<gemmBlocks, 256>>>(hbb, mbb, wbb, b1, h1bb, h18, K_NODES);

    // layer 2 on graph means: fused SpMM2 + per-graph sums, then readout
    k_spmm_gs2<<<K_NODES / 16, 512>>>(h18, h1bb, gid);
    k_hgcls<<<K_GRAPHS, K_DIM>>>(W2s, W2n, b2, perm, Wc, bc, out);
}